// round 5
// baseline (speedup 1.0000x reference)
#include <cuda_runtime.h>

// Problem constants: B=32, S=12, F=128, H=64, K=8, C=64, N=512
#define B_   32
#define S_   12
#define F_   128
#define H_   64
#define K_   8
#define C_   64
#define N_   512
#define KH_  (K_*H_)        // 512
#define WFC_ (N_*C_)        // 32768 floats per Wf row

// Scratch (no device mallocs allowed):
__device__ float g_Who[B_*C_];     // 2048 floats
__device__ float g_wfs[C_*C_];     // WfSum[c'][c], 4096 floats

// Kernel 1, 96 blocks x 1024 threads (proven config):
//  blocks [0,64):  WfSum[c',:] — each block streams one full 128KB Wf row
//  blocks [64,96): Who[b,:]    — GAT collapse (uniform softmax => att@Wh == Wh)
__global__ __launch_bounds__(1024) void k1(
    const float* __restrict__ x,        // (B, S, F)
    const float* __restrict__ W_heads,  // (K, F, H)
    const float* __restrict__ W_out,    // (K*H, C)
    const float* __restrict__ Wf)       // (C, N*C)
{
    const int t   = threadIdx.x;
    const int bid = blockIdx.x;

    if (bid < C_) {
        // ---- Wf row reduction: the only DRAM-heavy work (8.4 MB total) ----
        __shared__ float4 part4[1024];          // 16 KB
        const int cp = bid;
        const int c4 = t & 15;
        const int n0 = t >> 4;
        const float4* __restrict__ row = (const float4*)(Wf + (size_t)cp * WFC_);
        float4 s = make_float4(0.f, 0.f, 0.f, 0.f);
        #pragma unroll
        for (int i = 0; i < 8; ++i) {           // 8 independent float4 loads (128B in flight)
            float4 v = row[(size_t)(n0 + i * 64) * 16 + c4];
            s.x += v.x; s.y += v.y; s.z += v.z; s.w += v.w;
        }
        part4[t] = s;
        __syncthreads();
        if (t < C_) {
            const float* pf = (const float*)part4;
            float acc = 0.f;
            #pragma unroll
            for (int n0i = 0; n0i < 64; ++n0i) acc += pf[n0i * 64 + t];
            g_wfs[cp * C_ + t] = acc;
        }
    } else {
        // ---- Who[b,:] ----
        __shared__ float xs[F_];
        __shared__ float ws[1024];
        __shared__ float hcat[KH_];
        const int b = bid - C_;
        if (t < F_) xs[t] = x[(b * S_ + (S_ - 1)) * F_ + t];
        __syncthreads();
        {
            const int o    = t & 511;
            const int half = t >> 9;
            const int k    = o >> 6;
            const int h    = o & 63;
            const float* wp = W_heads + ((size_t)k * F_ + half * 64) * H_ + h;
            const float* xp = xs + half * 64;
            float acc = 0.f;
            #pragma unroll 8
            for (int f = 0; f < 64; ++f) acc = fmaf(xp[f], wp[(size_t)f * H_], acc);
            ws[t] = acc;
        }
        __syncthreads();
        if (t < KH_) {
            float v = ws[t] + ws[t + 512];
            hcat[t] = v > 0.f ? v : expm1f(v);   // ELU
        }
        __syncthreads();
        {
            const int c  = t & 63;
            const int j0 = t >> 6;
            float p = 0.f;
            #pragma unroll
            for (int j = j0; j < KH_; j += 16) p = fmaf(hcat[j], W_out[(size_t)j * C_ + c], p);
            ws[t] = p;
        }
        __syncthreads();
        if (t < C_) {
            float s2 = 0.f;
            #pragma unroll
            for (int g = 0; g < 16; ++g) s2 += ws[g * 64 + t];
            g_Who[b * C_ + t] = s2;
        }
    }

#if __CUDA_ARCH__ >= 900
    cudaTriggerProgrammaticLaunchCompletion();
#endif
}

// Kernel 2: barrier-free, smem-free. 2048 threads, one output each.
// PDL: launches early, syncs on k1 completion before reading its outputs.
__global__ __launch_bounds__(1024) void k2(
    const float* __restrict__ bf,
    float* __restrict__ out)
{
    const int idx = blockIdx.x * 1024 + threadIdx.x;  // 0..2047
    const int b   = idx >> 6;
    const int cp  = idx & 63;
    const float bias = bf[cp];                        // harness input: safe pre-sync

#if __CUDA_ARCH__ >= 900
    cudaGridDependencySynchronize();                  // wait for k1's writes
#endif

    const float4* __restrict__ w4 = ((const float4*)g_wfs) + cp * 16;
    const float4* __restrict__ h4 = ((const float4*)g_Who) + b * 16;

    float a0 = 0.f, a1 = 0.f, a2 = 0.f, a3 = 0.f;
    #pragma unroll
    for (int i = 0; i < 16; ++i) {
        const float4 w = w4[i];
        const float4 h = h4[i];
        a0 = fmaf(h.x, w.x, a0);
        a1 = fmaf(h.y, w.y, a1);
        a2 = fmaf(h.z, w.z, a2);
        a3 = fmaf(h.w, w.w, a3);
    }
    out[idx] = bias + ((a0 + a1) + (a2 + a3));
}

extern "C" void kernel_launch(void* const* d_in, const int* in_sizes, int n_in,
                              void* d_out, int out_size)
{
    const float* x       = (const float*)d_in[0]; // (32,12,128)
    const float* W_heads = (const float*)d_in[1]; // (8,128,64)
    // d_in[2], d_in[3]: a1_heads/a2_heads — unused (uniform softmax)
    const float* W_out   = (const float*)d_in[4]; // (512,64)
    // d_in[5], d_in[6]: a1_out/a2_out — unused
    const float* Wf      = (const float*)d_in[7]; // (64, 32768)
    const float* bf      = (const float*)d_in[8]; // (64,)
    float* out = (float*)d_out;                   // (32,64)

    k1<<<C_ + B_, 1024>>>(x, W_heads, W_out, Wf);

    // k2 with programmatic dependent launch: its launch latency overlaps k1.
    cudaLaunchConfig_t cfg = {};
    cfg.gridDim  = dim3(2, 1, 1);
    cfg.blockDim = dim3(1024, 1, 1);
    cfg.dynamicSmemBytes = 0;
    cfg.stream = 0;   // legacy default stream (same one the harness captures)
    cudaLaunchAttribute attrs[1];
    attrs[0].id = cudaLaunchAttributeProgrammaticStreamSerialization;
    attrs[0].val.programmaticStreamSerializationAllowed = 1;
    cfg.attrs = attrs;
    cfg.numAttrs = 1;
    cudaLaunchKernelEx(&cfg, k2, bf, out);
}

// round 8
// speedup vs baseline: 1.4521x; 1.4521x over previous
#include <cuda_runtime.h>

// Problem constants: B=32, S=12, F=128, H=64, K=8, C=64, N=512
#define B_   32
#define S_   12
#define F_   128
#define H_   64
#define K_   8
#define C_   64
#define N_   512
#define KH_  (K_*H_)        // 512
#define WFC_ (N_*C_)        // 32768 floats per Wf row

// Scratch (device globals; zero-init, reset in-kernel each run):
__device__ float g_Who[B_*C_];          // 2048 floats
__device__ unsigned int g_count;        // Who-producer arrivals (0..32)
__device__ unsigned int g_done;         // Wf-consumer arrivals  (0..64)

// ONE kernel, 96 blocks x 1024 threads, single wave (96 < 148 SMs => all
// blocks co-resident => producer/consumer spin is deadlock-free):
//   blocks [0,64):  stream Wf row cp (128KB), reduce to WfSum[cp,:], then wait
//                   for the 32 Who producers and emit output column out[:,cp].
//   blocks [64,96): GAT collapse -> g_Who[b,:]  (softmax over identical node
//                   rows is exactly uniform => att @ Wh == Wh, both layers).
__global__ __launch_bounds__(1024) void k_all(
    const float* __restrict__ x,        // (B, S, F)
    const float* __restrict__ W_heads,  // (K, F, H)
    const float* __restrict__ W_out,    // (K*H, C)
    const float* __restrict__ Wf,       // (C, N*C)
    const float* __restrict__ bf,       // (C,)
    float* __restrict__ out)            // (B, C)
{
    __shared__ __align__(16) float sm[4096];    // 16KB, aliased per phase
    __shared__ float wfs_s[C_];

    const int t   = threadIdx.x;
    const int bid = blockIdx.x;

    if (bid >= C_) {
        // ================= Who producer (b = bid-64) =================
        float* xs   = sm;                // 128
        float* ws   = sm + 128;          // 1024
        float* hcat = sm + 1152;         // 512
        const int b = bid - C_;
        if (t < F_) xs[t] = x[(b * S_ + (S_ - 1)) * F_ + t];
        __syncthreads();
        {   // Wh[k,h], each output split across 2 threads (64 f's each)
            const int o    = t & 511;
            const int half = t >> 9;
            const int k    = o >> 6;
            const int h    = o & 63;
            const float* wp = W_heads + ((size_t)k * F_ + half * 64) * H_ + h;
            const float* xp = xs + half * 64;
            float acc = 0.f;
            #pragma unroll 8
            for (int f = 0; f < 64; ++f) acc = fmaf(xp[f], wp[(size_t)f * H_], acc);
            ws[t] = acc;
        }
        __syncthreads();
        if (t < KH_) {
            float v = ws[t] + ws[t + 512];
            hcat[t] = v > 0.f ? v : expm1f(v);        // ELU
        }
        __syncthreads();
        {   // Who[c] = sum_j hcat[j] * W_out[j,c], j split 16 ways
            const int c  = t & 63;
            const int j0 = t >> 6;
            float p = 0.f;
            #pragma unroll
            for (int j = j0; j < KH_; j += 16)
                p = fmaf(hcat[j], W_out[(size_t)j * C_ + c], p);
            ws[t] = p;
        }
        __syncthreads();
        if (t < C_) {
            float s2 = 0.f;
            #pragma unroll
            for (int g = 0; g < 16; ++g) s2 += ws[g * 64 + t];
            g_Who[b * C_ + t] = s2;
        }
        __syncthreads();
        if (t == 0) {
            __threadfence();                  // release g_Who writes
            atomicAdd(&g_count, 1u);          // signal (32 cheap atomics total)
        }
        return;
    }

    // ================= Wf streamer + output column cp =================
    const int cp = bid;
    {
        // stream one 128KB row: 8 independent float4 loads / thread
        const int c4 = t & 15;
        const int n0 = t >> 4;
        const float4* __restrict__ row = (const float4*)(Wf + (size_t)cp * WFC_);
        float4 s = make_float4(0.f, 0.f, 0.f, 0.f);
        #pragma unroll
        for (int i = 0; i < 8; ++i) {
            float4 v = row[(size_t)(n0 + i * 64) * 16 + c4];
            s.x += v.x; s.y += v.y; s.z += v.z; s.w += v.w;
        }
        ((float4*)sm)[t] = s;
    }
    const float bias = bf[cp];                // prefetch while smem settles
    __syncthreads();
    if (t < C_) {
        float acc = 0.f;
        #pragma unroll
        for (int n = 0; n < 64; ++n) acc += sm[n * 64 + t];
        wfs_s[t] = acc;                       // WfSum[cp, t]
    }

    // wait for all 32 Who producers (they run concurrently; usually done)
    if (t == 0) {
        while (*(volatile unsigned int*)&g_count < (unsigned)B_) __nanosleep(64);
    }
    __syncthreads();
    __threadfence();                          // acquire side of the flag

    // stage g_Who (2048 floats) into smem with +1 row padding.
    // 1024 threads => TWO iterations (this was the R6 bug: only one ran).
    {
        float* who_s = sm;                    // reuse: 32 rows x 65 = 2080 floats
        #pragma unroll
        for (int rep = 0; rep < 2; ++rep) {
            const int i = t + rep * 1024;     // 0..2047
            const int b = i >> 6, c = i & 63;
            who_s[b * 65 + c] = __ldcg(&g_Who[i]);
        }
        __syncthreads();
        if (t < B_) {
            const float* hr = who_s + t * 65;
            float acc = bias;
            #pragma unroll 8
            for (int c = 0; c < C_; ++c) acc = fmaf(hr[c], wfs_s[c], acc);
            out[t * C_ + cp] = acc;
        }
    }

    // counter reset for next graph replay: last of the 64 consumers cleans up
    __syncthreads();
    if (t == 0) {
        unsigned int d = atomicAdd(&g_done, 1u);
        if (d == (unsigned)(C_ - 1)) {
            g_count = 0u;
            g_done  = 0u;
            __threadfence();
        }
    }
}

extern "C" void kernel_launch(void* const* d_in, const int* in_sizes, int n_in,
                              void* d_out, int out_size)
{
    const float* x       = (const float*)d_in[0]; // (32,12,128)
    const float* W_heads = (const float*)d_in[1]; // (8,128,64)
    // d_in[2], d_in[3]: a1_heads/a2_heads — unused (uniform softmax)
    const float* W_out   = (const float*)d_in[4]; // (512,64)
    // d_in[5], d_in[6]: a1_out/a2_out — unused
    const float* Wf      = (const float*)d_in[7]; // (64, 32768)
    const float* bf      = (const float*)d_in[8]; // (64,)
    float* out = (float*)d_out;                   // (32,64)

    k_all<<<C_ + B_, 1024>>>(x, W_heads, W_out, Wf, bf, out);
}